// round 8
// baseline (speedup 1.0000x reference)
#include <cuda_runtime.h>

// BatchNorm over features: X[N, D], stats over axis 0.
// N = 131072, D = 512, fp32 in/out.
//
// Round 6: resubmission of Round 5 (infra failure, never measured).
// Single-wave persistent grids (296 blocks = 148 SMs x occ 2) with
// fine-grained 16-row chunk striding to kill wave-quantization tails
// (previously 1.73 / 3.46 waves). Streaming cache hints on the big streams.

#define NROWS  131072
#define DCOLS  512
#define DV     128                   // DCOLS / 4 (float4 quads per row)
#define CHROWS 16                    // rows per chunk
#define NCHUNK (NROWS / CHROWS)      // 8192 chunks
#define GRID1  296                   // persistent blocks (148 SMs * 2)

// Scratch (__device__ globals; allocation is forbidden).
// Partials transposed: g_psum[col * GRID1 + block] for coalesced finalize reads.
__device__ float g_psum[DCOLS * GRID1];
__device__ float g_psq [DCOLS * GRID1];
__device__ __align__(16) float g_scale[DCOLS];
__device__ __align__(16) float g_shift[DCOLS];

// ---------------------------------------------------------------------------
// Pass 1: persistent blocks stride over 16-row chunks. 512 threads =
// 128 column-quads x 4 row-lanes; each thread accumulates 4 columns.
// ---------------------------------------------------------------------------
__global__ __launch_bounds__(512, 2)
void bn_reduce_kernel(const float4* __restrict__ Xv) {
    const int b   = blockIdx.x;
    const int tid = threadIdx.x;
    const int cq  = tid & 127;   // column quad 0..127
    const int lr  = tid >> 7;    // row lane   0..3

    float sx = 0.f, sy = 0.f, sz = 0.f, sw = 0.f;
    float qx = 0.f, qy = 0.f, qz = 0.f, qw = 0.f;

    for (int c = b; c < NCHUNK; c += GRID1) {
        size_t base = ((size_t)c * CHROWS + (size_t)lr) * DV + (size_t)cq;
        float4 x0 = __ldcs(&Xv[base + 0 * 4 * DV]);
        float4 x1 = __ldcs(&Xv[base + 1 * 4 * DV]);
        float4 x2 = __ldcs(&Xv[base + 2 * 4 * DV]);
        float4 x3 = __ldcs(&Xv[base + 3 * 4 * DV]);

        sx += x0.x; sy += x0.y; sz += x0.z; sw += x0.w;
        qx = fmaf(x0.x, x0.x, qx); qy = fmaf(x0.y, x0.y, qy);
        qz = fmaf(x0.z, x0.z, qz); qw = fmaf(x0.w, x0.w, qw);

        sx += x1.x; sy += x1.y; sz += x1.z; sw += x1.w;
        qx = fmaf(x1.x, x1.x, qx); qy = fmaf(x1.y, x1.y, qy);
        qz = fmaf(x1.z, x1.z, qz); qw = fmaf(x1.w, x1.w, qw);

        sx += x2.x; sy += x2.y; sz += x2.z; sw += x2.w;
        qx = fmaf(x2.x, x2.x, qx); qy = fmaf(x2.y, x2.y, qy);
        qz = fmaf(x2.z, x2.z, qz); qw = fmaf(x2.w, x2.w, qw);

        sx += x3.x; sy += x3.y; sz += x3.z; sw += x3.w;
        qx = fmaf(x3.x, x3.x, qx); qy = fmaf(x3.y, x3.y, qy);
        qz = fmaf(x3.z, x3.z, qz); qw = fmaf(x3.w, x3.w, qw);
    }

    __shared__ float4 shs[512];
    __shared__ float4 shq[512];
    shs[tid] = make_float4(sx, sy, sz, sw);
    shq[tid] = make_float4(qx, qy, qz, qw);
    __syncthreads();

    if (lr == 0) {
        float4 s = shs[cq];
        float4 q = shq[cq];
        #pragma unroll
        for (int k = 1; k < 4; k++) {
            float4 a  = shs[cq + 128 * k];
            float4 c2 = shq[cq + 128 * k];
            s.x += a.x; s.y += a.y; s.z += a.z; s.w += a.w;
            q.x += c2.x; q.y += c2.y; q.z += c2.z; q.w += c2.w;
        }
        const int c0 = 4 * cq;
        g_psum[(size_t)(c0 + 0) * GRID1 + b] = s.x;
        g_psum[(size_t)(c0 + 1) * GRID1 + b] = s.y;
        g_psum[(size_t)(c0 + 2) * GRID1 + b] = s.z;
        g_psum[(size_t)(c0 + 3) * GRID1 + b] = s.w;
        g_psq [(size_t)(c0 + 0) * GRID1 + b] = q.x;
        g_psq [(size_t)(c0 + 1) * GRID1 + b] = q.y;
        g_psq [(size_t)(c0 + 2) * GRID1 + b] = q.z;
        g_psq [(size_t)(c0 + 3) * GRID1 + b] = q.w;
    }
}

// ---------------------------------------------------------------------------
// Stage 2: one block per column; 128 threads reduce GRID1=296 partials,
// then fold stats + gamma/beta into scale/shift.
// ---------------------------------------------------------------------------
__global__ __launch_bounds__(128)
void bn_finalize_kernel(const float* __restrict__ gamma,
                        const float* __restrict__ beta,
                        float inv_n) {
    const int c = blockIdx.x;
    const int t = threadIdx.x;

    float s = 0.f, q = 0.f;
    for (int i = t; i < GRID1; i += 128) {
        s += g_psum[(size_t)c * GRID1 + i];
        q += g_psq [(size_t)c * GRID1 + i];
    }

    #pragma unroll
    for (int off = 16; off > 0; off >>= 1) {
        s += __shfl_down_sync(0xFFFFFFFFu, s, off);
        q += __shfl_down_sync(0xFFFFFFFFu, q, off);
    }

    __shared__ float ss[4];
    __shared__ float sq[4];
    const int warp = t >> 5;
    const int lane = t & 31;
    if (lane == 0) { ss[warp] = s; sq[warp] = q; }
    __syncthreads();

    if (t == 0) {
        s = ss[0] + ss[1] + ss[2] + ss[3];
        q = sq[0] + sq[1] + sq[2] + sq[3];
        float mean = s * inv_n;
        float var  = fmaf(-mean, mean, q * inv_n);   // E[x^2] - mean^2
        float inv  = rsqrtf(var);                    // no epsilon (matches reference)
        float sc   = inv * gamma[c];
        g_scale[c] = sc;
        g_shift[c] = fmaf(-mean, sc, beta[c]);
    }
}

// ---------------------------------------------------------------------------
// Pass 2: persistent blocks stride over 16-row chunks.
// Y = X * scale + shift with streaming load/store hints.
// ---------------------------------------------------------------------------
__global__ __launch_bounds__(512, 2)
void bn_normalize_kernel(const float4* __restrict__ Xv, float4* __restrict__ Yv) {
    const int b   = blockIdx.x;
    const int tid = threadIdx.x;
    const int cq  = tid & 127;
    const int lr  = tid >> 7;

    const float4 sc = reinterpret_cast<const float4*>(g_scale)[cq];
    const float4 sh = reinterpret_cast<const float4*>(g_shift)[cq];

    for (int c = b; c < NCHUNK; c += GRID1) {
        size_t base = ((size_t)c * CHROWS + (size_t)lr) * DV + (size_t)cq;
        #pragma unroll
        for (int r = 0; r < 4; r++) {
            size_t idx = base + (size_t)r * (4 * DV);
            float4 x = __ldcs(&Xv[idx]);
            float4 y;
            y.x = fmaf(x.x, sc.x, sh.x);
            y.y = fmaf(x.y, sc.y, sh.y);
            y.z = fmaf(x.z, sc.z, sh.z);
            y.w = fmaf(x.w, sc.w, sh.w);
            __stcs(&Yv[idx], y);
        }
    }
}

// ---------------------------------------------------------------------------
extern "C" void kernel_launch(void* const* d_in, const int* in_sizes, int n_in,
                              void* d_out, int out_size) {
    const float* X     = (const float*)d_in[0];
    const float* gamma = (const float*)d_in[1];
    const float* beta  = (const float*)d_in[2];
    float*       Y     = (float*)d_out;

    bn_reduce_kernel<<<GRID1, 512>>>((const float4*)X);
    bn_finalize_kernel<<<DCOLS, 128>>>(gamma, beta, 1.0f / (float)NROWS);
    bn_normalize_kernel<<<GRID1, 512>>>((const float4*)X, (float4*)Y);
}

// round 9
// speedup vs baseline: 1.1324x; 1.1324x over previous
#include <cuda_runtime.h>

// BatchNorm over features: X[N, D], stats over axis 0.
// N = 131072, D = 512, fp32 in/out.
//
// Round 8 post-mortem applied:
//  - REVERT normalize to the known-good R2 form (1024 blocks, flat unroll-8
//    stream, plain loads/stores). The persistent-grid + __stcs version cost
//    ~20us; wave quantization was a phantom (block scheduling is fluid).
//  - reduce: batch 8 float4 loads per iteration (was 4) to double in-flight
//    bytes per SM (16KB -> 32KB), targeting the latency-MLP budget that holds
//    it at 78% DRAM.

#define NROWS 131072
#define DCOLS 512
#define DV    128            // DCOLS / 4 (float4 quads per row)
#define RB1   256            // rows per block, pass 1
#define NB1   (NROWS / RB1)  // 512 blocks in pass 1
#define RB2   128            // rows per block, pass 2
#define NB2   (NROWS / RB2)  // 1024 blocks in pass 2

// Scratch (__device__ globals; allocation is forbidden).
// Partials transposed: g_psum[col * NB1 + block] for coalesced finalize reads.
__device__ float g_psum[DCOLS * NB1];
__device__ float g_psq [DCOLS * NB1];
__device__ __align__(16) float g_scale[DCOLS];
__device__ __align__(16) float g_shift[DCOLS];

// ---------------------------------------------------------------------------
// Pass 1: each block owns RB1=256 consecutive rows. 512 threads = 128 column
// quads x 4 row-lanes; each thread covers 64 rows of its 4 columns.
// 8 float4 loads are batched up front per iteration for MLP=8/thread.
// ---------------------------------------------------------------------------
__global__ __launch_bounds__(512, 2)
void bn_reduce_kernel(const float4* __restrict__ Xv) {
    const int b   = blockIdx.x;
    const int tid = threadIdx.x;
    const int cq  = tid & 127;   // column quad 0..127
    const int lr  = tid >> 7;    // row lane   0..3

    float sx = 0.f, sy = 0.f, sz = 0.f, sw = 0.f;
    float qx = 0.f, qy = 0.f, qz = 0.f, qw = 0.f;

    size_t base = ((size_t)b * RB1 + (size_t)lr) * DV + (size_t)cq;

    #pragma unroll
    for (int i = 0; i < 8; i++) {
        // Batch 8 independent 16B loads before any consumption.
        float4 x[8];
        #pragma unroll
        for (int j = 0; j < 8; j++) {
            x[j] = Xv[base + (size_t)(i * 8 + j) * (4 * DV)];
        }
        #pragma unroll
        for (int j = 0; j < 8; j++) {
            sx += x[j].x; sy += x[j].y; sz += x[j].z; sw += x[j].w;
            qx = fmaf(x[j].x, x[j].x, qx);
            qy = fmaf(x[j].y, x[j].y, qy);
            qz = fmaf(x[j].z, x[j].z, qz);
            qw = fmaf(x[j].w, x[j].w, qw);
        }
    }

    __shared__ float4 shs[512];
    __shared__ float4 shq[512];
    shs[tid] = make_float4(sx, sy, sz, sw);
    shq[tid] = make_float4(qx, qy, qz, qw);
    __syncthreads();

    if (lr == 0) {
        float4 s = shs[cq];
        float4 q = shq[cq];
        #pragma unroll
        for (int k = 1; k < 4; k++) {
            float4 a  = shs[cq + 128 * k];
            float4 c2 = shq[cq + 128 * k];
            s.x += a.x; s.y += a.y; s.z += a.z; s.w += a.w;
            q.x += c2.x; q.y += c2.y; q.z += c2.z; q.w += c2.w;
        }
        const int c0 = 4 * cq;
        g_psum[(size_t)(c0 + 0) * NB1 + b] = s.x;
        g_psum[(size_t)(c0 + 1) * NB1 + b] = s.y;
        g_psum[(size_t)(c0 + 2) * NB1 + b] = s.z;
        g_psum[(size_t)(c0 + 3) * NB1 + b] = s.w;
        g_psq [(size_t)(c0 + 0) * NB1 + b] = q.x;
        g_psq [(size_t)(c0 + 1) * NB1 + b] = q.y;
        g_psq [(size_t)(c0 + 2) * NB1 + b] = q.z;
        g_psq [(size_t)(c0 + 3) * NB1 + b] = q.w;
    }
}

// ---------------------------------------------------------------------------
// Stage 2: one block per column; 256 threads reduce NB1=512 partials, then
// fold stats + gamma/beta into scale/shift.
// ---------------------------------------------------------------------------
__global__ __launch_bounds__(256)
void bn_finalize_kernel(const float* __restrict__ gamma,
                        const float* __restrict__ beta,
                        float inv_n) {
    const int c = blockIdx.x;
    const int t = threadIdx.x;

    float s = g_psum[(size_t)c * NB1 + t] + g_psum[(size_t)c * NB1 + t + 256];
    float q = g_psq [(size_t)c * NB1 + t] + g_psq [(size_t)c * NB1 + t + 256];

    #pragma unroll
    for (int off = 16; off > 0; off >>= 1) {
        s += __shfl_down_sync(0xFFFFFFFFu, s, off);
        q += __shfl_down_sync(0xFFFFFFFFu, q, off);
    }

    __shared__ float ss[8];
    __shared__ float sq[8];
    const int warp = t >> 5;
    const int lane = t & 31;
    if (lane == 0) { ss[warp] = s; sq[warp] = q; }
    __syncthreads();

    if (t < 8) {
        s = ss[t];
        q = sq[t];
        #pragma unroll
        for (int off = 4; off > 0; off >>= 1) {
            s += __shfl_down_sync(0x000000FFu, s, off);
            q += __shfl_down_sync(0x000000FFu, q, off);
        }
        if (t == 0) {
            float mean = s * inv_n;
            float var  = fmaf(-mean, mean, q * inv_n);  // E[x^2] - mean^2
            float inv  = rsqrtf(var);                   // no epsilon (matches reference)
            float sc   = inv * gamma[c];
            g_scale[c] = sc;
            g_shift[c] = fmaf(-mean, sc, beta[c]);
        }
    }
}

// ---------------------------------------------------------------------------
// Pass 2 (known-good R2 form): each block owns RB2=128 rows; flat unroll-8
// float4 load + FMA + store stream. No cache hints.
// ---------------------------------------------------------------------------
__global__ __launch_bounds__(512, 2)
void bn_normalize_kernel(const float4* __restrict__ Xv, float4* __restrict__ Yv) {
    const int b   = blockIdx.x;
    const int tid = threadIdx.x;
    const int cq  = tid & 127;
    const int lr  = tid >> 7;

    const float4 sc = reinterpret_cast<const float4*>(g_scale)[cq];
    const float4 sh = reinterpret_cast<const float4*>(g_shift)[cq];

    size_t base = ((size_t)b * RB2 + (size_t)lr) * DV + (size_t)cq;
    #pragma unroll 8
    for (int r = 0; r < RB2 / 4; r++) {
        size_t idx = base + (size_t)r * (4 * DV);
        float4 x = Xv[idx];
        float4 y;
        y.x = fmaf(x.x, sc.x, sh.x);
        y.y = fmaf(x.y, sc.y, sh.y);
        y.z = fmaf(x.z, sc.z, sh.z);
        y.w = fmaf(x.w, sc.w, sh.w);
        Yv[idx] = y;
    }
}

// ---------------------------------------------------------------------------
extern "C" void kernel_launch(void* const* d_in, const int* in_sizes, int n_in,
                              void* d_out, int out_size) {
    const float* X     = (const float*)d_in[0];
    const float* gamma = (const float*)d_in[1];
    const float* beta  = (const float*)d_in[2];
    float*       Y     = (float*)d_out;

    bn_reduce_kernel<<<NB1, 512>>>((const float4*)X);
    bn_finalize_kernel<<<DCOLS, 256>>>(gamma, beta, 1.0f / (float)NROWS);
    bn_normalize_kernel<<<NB2, 512>>>((const float4*)X, (float4*)Y);
}

// round 10
// speedup vs baseline: 1.1705x; 1.0336x over previous
#include <cuda_runtime.h>

// BatchNorm over features: X[N, D], stats over axis 0.
// N = 131072, D = 512, fp32 in/out.
//
// Round 9 post-mortem:
//  - reduce reverted to R2 form (best measured: 44.3us). MLP batching and
//    persistent grids are all within noise of the ~6.2TB/s HBM ceiling.
//  - Only remaining lever is cross-kernel L2 reuse: after reduce, the tail
//    ~110MB of X is L2-resident (default cache policy, in-order completion).
//    Pass 2 therefore iterates blocks in REVERSE so its first blocks read the
//    resident tail, and uses __stcs for Y stores so write-allocate traffic
//    doesn't evict X while it's being harvested.

#define NROWS 131072
#define DCOLS 512
#define DV    128            // DCOLS / 4 (float4 quads per row)
#define RB1   256            // rows per block, pass 1
#define NB1   (NROWS / RB1)  // 512 blocks in pass 1
#define RB2   128            // rows per block, pass 2
#define NB2   (NROWS / RB2)  // 1024 blocks in pass 2

// Scratch (__device__ globals; allocation is forbidden).
// Partials transposed: g_psum[col * NB1 + block] for coalesced finalize reads.
__device__ float g_psum[DCOLS * NB1];
__device__ float g_psq [DCOLS * NB1];
__device__ __align__(16) float g_scale[DCOLS];
__device__ __align__(16) float g_shift[DCOLS];

// ---------------------------------------------------------------------------
// Pass 1 (R2 form): each block owns RB1=256 consecutive rows. 512 threads =
// 128 column-quads x 4 row-lanes; each thread covers 64 rows of 4 columns.
// Default cache policy so the tail of X stays L2-resident for pass 2.
// ---------------------------------------------------------------------------
__global__ __launch_bounds__(512, 2)
void bn_reduce_kernel(const float4* __restrict__ Xv) {
    const int b   = blockIdx.x;
    const int tid = threadIdx.x;
    const int cq  = tid & 127;   // column quad 0..127
    const int lr  = tid >> 7;    // row lane   0..3

    float sx = 0.f, sy = 0.f, sz = 0.f, sw = 0.f;
    float qx = 0.f, qy = 0.f, qz = 0.f, qw = 0.f;

    size_t base = ((size_t)b * RB1 + (size_t)lr) * DV + (size_t)cq;
    #pragma unroll 8
    for (int r = 0; r < RB1 / 4; r++) {
        float4 x = Xv[base + (size_t)r * (4 * DV)];
        sx += x.x; sy += x.y; sz += x.z; sw += x.w;
        qx = fmaf(x.x, x.x, qx);
        qy = fmaf(x.y, x.y, qy);
        qz = fmaf(x.z, x.z, qz);
        qw = fmaf(x.w, x.w, qw);
    }

    __shared__ float4 shs[512];
    __shared__ float4 shq[512];
    shs[tid] = make_float4(sx, sy, sz, sw);
    shq[tid] = make_float4(qx, qy, qz, qw);
    __syncthreads();

    if (lr == 0) {
        float4 s = shs[cq];
        float4 q = shq[cq];
        #pragma unroll
        for (int k = 1; k < 4; k++) {
            float4 a  = shs[cq + 128 * k];
            float4 c2 = shq[cq + 128 * k];
            s.x += a.x; s.y += a.y; s.z += a.z; s.w += a.w;
            q.x += c2.x; q.y += c2.y; q.z += c2.z; q.w += c2.w;
        }
        const int c0 = 4 * cq;
        g_psum[(size_t)(c0 + 0) * NB1 + b] = s.x;
        g_psum[(size_t)(c0 + 1) * NB1 + b] = s.y;
        g_psum[(size_t)(c0 + 2) * NB1 + b] = s.z;
        g_psum[(size_t)(c0 + 3) * NB1 + b] = s.w;
        g_psq [(size_t)(c0 + 0) * NB1 + b] = q.x;
        g_psq [(size_t)(c0 + 1) * NB1 + b] = q.y;
        g_psq [(size_t)(c0 + 2) * NB1 + b] = q.z;
        g_psq [(size_t)(c0 + 3) * NB1 + b] = q.w;
    }
}

// ---------------------------------------------------------------------------
// Stage 2: one block per column; 256 threads reduce NB1=512 partials, then
// fold stats + gamma/beta into scale/shift.
// ---------------------------------------------------------------------------
__global__ __launch_bounds__(256)
void bn_finalize_kernel(const float* __restrict__ gamma,
                        const float* __restrict__ beta,
                        float inv_n) {
    const int c = blockIdx.x;
    const int t = threadIdx.x;

    float s = g_psum[(size_t)c * NB1 + t] + g_psum[(size_t)c * NB1 + t + 256];
    float q = g_psq [(size_t)c * NB1 + t] + g_psq [(size_t)c * NB1 + t + 256];

    #pragma unroll
    for (int off = 16; off > 0; off >>= 1) {
        s += __shfl_down_sync(0xFFFFFFFFu, s, off);
        q += __shfl_down_sync(0xFFFFFFFFu, q, off);
    }

    __shared__ float ss[8];
    __shared__ float sq[8];
    const int warp = t >> 5;
    const int lane = t & 31;
    if (lane == 0) { ss[warp] = s; sq[warp] = q; }
    __syncthreads();

    if (t < 8) {
        s = ss[t];
        q = sq[t];
        #pragma unroll
        for (int off = 4; off > 0; off >>= 1) {
            s += __shfl_down_sync(0x000000FFu, s, off);
            q += __shfl_down_sync(0x000000FFu, q, off);
        }
        if (t == 0) {
            float mean = s * inv_n;
            float var  = fmaf(-mean, mean, q * inv_n);  // E[x^2] - mean^2
            float inv  = rsqrtf(var);                   // no epsilon (matches reference)
            float sc   = inv * gamma[c];
            g_scale[c] = sc;
            g_shift[c] = fmaf(-mean, sc, beta[c]);
        }
    }
}

// ---------------------------------------------------------------------------
// Pass 2: R2 flat form, but blocks iterate X in REVERSE so the first blocks
// hit the L2-resident tail left by pass 1. Y stores use __stcs so the write
// stream doesn't evict still-useful X lines.
// ---------------------------------------------------------------------------
__global__ __launch_bounds__(512, 2)
void bn_normalize_kernel(const float4* __restrict__ Xv, float4* __restrict__ Yv) {
    const int b   = NB2 - 1 - blockIdx.x;   // reverse order for L2 reuse
    const int tid = threadIdx.x;
    const int cq  = tid & 127;
    const int lr  = tid >> 7;

    const float4 sc = reinterpret_cast<const float4*>(g_scale)[cq];
    const float4 sh = reinterpret_cast<const float4*>(g_shift)[cq];

    size_t base = ((size_t)b * RB2 + (size_t)lr) * DV + (size_t)cq;
    #pragma unroll 8
    for (int r = 0; r < RB2 / 4; r++) {
        size_t idx = base + (size_t)r * (4 * DV);
        float4 x = Xv[idx];
        float4 y;
        y.x = fmaf(x.x, sc.x, sh.x);
        y.y = fmaf(x.y, sc.y, sh.y);
        y.z = fmaf(x.z, sc.z, sh.z);
        y.w = fmaf(x.w, sc.w, sh.w);
        __stcs(&Yv[idx], y);
    }
}

// ---------------------------------------------------------------------------
extern "C" void kernel_launch(void* const* d_in, const int* in_sizes, int n_in,
                              void* d_out, int out_size) {
    const float* X     = (const float*)d_in[0];
    const float* gamma = (const float*)d_in[1];
    const float* beta  = (const float*)d_in[2];
    float*       Y     = (float*)d_out;

    bn_reduce_kernel<<<NB1, 512>>>((const float4*)X);
    bn_finalize_kernel<<<DCOLS, 256>>>(gamma, beta, 1.0f / (float)NROWS);
    bn_normalize_kernel<<<NB2, 512>>>((const float4*)X, (float4*)Y);
}

// round 11
// speedup vs baseline: 1.2084x; 1.0324x over previous
#include <cuda_runtime.h>

// BatchNorm over features: X[N, D], stats over axis 0. N=131072, D=512, fp32.
//
// Round 11: single fused persistent kernel (296 blocks, all co-resident) with
// a software grid barrier. Each block owns a contiguous region of X; phase 1
// reduces it front-to-back, phase 2 normalizes it BACK-TO-FRONT so reads
// consume L2 lines in exact reverse recency order (LIFO vs LRU -> max hits).
// Finalize runs in-kernel between two barriers. Y stores use __stcs.

#define NROWS  131072
#define DCOLS  512
#define DV     128                  // DCOLS/4 float4 quads per row
#define GRID   296                  // 2 blocks/SM x 148 SMs (GB300 has 152)
#define NTH    512
#define NCH16  (NROWS / 16)         // 8192 16-row chunks

// Scratch (__device__ globals; allocation forbidden).
__device__ float g_psum[DCOLS * GRID];   // [col * GRID + block]
__device__ float g_psq [DCOLS * GRID];
__device__ __align__(16) float g_scale[DCOLS];
__device__ __align__(16) float g_shift[DCOLS];
__device__ unsigned g_bar0;
__device__ unsigned g_bar1;

// Reset barrier state every launch (graph replays need pristine counters).
__global__ void bn_init_kernel() { g_bar0 = 0u; g_bar1 = 0u; }

// Grid-wide barrier: release-fence + relaxed atomic arrive, acquire-load spin.
// Requires all GRID blocks co-resident (guaranteed: occ 2, grid = 2*148).
__device__ __forceinline__ void grid_barrier(unsigned* ctr, int tid) {
    __syncthreads();
    if (tid == 0) {
        __threadfence();                       // release prior global writes
        atomicAdd(ctr, 1u);
        unsigned v;
        do {
            asm volatile("ld.acquire.gpu.u32 %0, [%1];"
                         : "=r"(v) : "l"(ctr) : "memory");
            if (v >= GRID) break;
            __nanosleep(64);
        } while (true);
    }
    __syncthreads();
}

__global__ __launch_bounds__(NTH, 2)
void bn_fused_kernel(const float4* __restrict__ Xv, float4* __restrict__ Yv,
                     const float* __restrict__ gamma,
                     const float* __restrict__ beta) {
    const int b   = blockIdx.x;
    const int tid = threadIdx.x;
    const int cq  = tid & 127;   // column quad 0..127
    const int lr  = tid >> 7;    // row lane   0..3

    // Contiguous region: chunks [cs, ce) of 16 rows each (27 or 28 chunks).
    const int cs = (int)(((long long)b       * NCH16) / GRID);
    const int ce = (int)(((long long)(b + 1) * NCH16) / GRID);
    const int rs = cs * 16;
    const int nIter = (ce - cs) * 4;    // float4-rows per lane (mult of 4)

    const size_t base = ((size_t)rs + (size_t)lr) * DV + (size_t)cq;

    // ---------------- Phase 1: reduce region front-to-back ----------------
    float sx = 0.f, sy = 0.f, sz = 0.f, sw = 0.f;
    float qx = 0.f, qy = 0.f, qz = 0.f, qw = 0.f;

    for (int i = 0; i < nIter; i += 4) {
        float4 x0 = Xv[base + (size_t)(i + 0) * (4 * DV)];
        float4 x1 = Xv[base + (size_t)(i + 1) * (4 * DV)];
        float4 x2 = Xv[base + (size_t)(i + 2) * (4 * DV)];
        float4 x3 = Xv[base + (size_t)(i + 3) * (4 * DV)];

        sx += x0.x; sy += x0.y; sz += x0.z; sw += x0.w;
        qx = fmaf(x0.x, x0.x, qx); qy = fmaf(x0.y, x0.y, qy);
        qz = fmaf(x0.z, x0.z, qz); qw = fmaf(x0.w, x0.w, qw);

        sx += x1.x; sy += x1.y; sz += x1.z; sw += x1.w;
        qx = fmaf(x1.x, x1.x, qx); qy = fmaf(x1.y, x1.y, qy);
        qz = fmaf(x1.z, x1.z, qz); qw = fmaf(x1.w, x1.w, qw);

        sx += x2.x; sy += x2.y; sz += x2.z; sw += x2.w;
        qx = fmaf(x2.x, x2.x, qx); qy = fmaf(x2.y, x2.y, qy);
        qz = fmaf(x2.z, x2.z, qz); qw = fmaf(x2.w, x2.w, qw);

        sx += x3.x; sy += x3.y; sz += x3.z; sw += x3.w;
        qx = fmaf(x3.x, x3.x, qx); qy = fmaf(x3.y, x3.y, qy);
        qz = fmaf(x3.z, x3.z, qz); qw = fmaf(x3.w, x3.w, qw);
    }

    {
        __shared__ float4 shs[NTH];
        __shared__ float4 shq[NTH];
        shs[tid] = make_float4(sx, sy, sz, sw);
        shq[tid] = make_float4(qx, qy, qz, qw);
        __syncthreads();

        if (lr == 0) {
            float4 s = shs[cq];
            float4 q = shq[cq];
            #pragma unroll
            for (int k = 1; k < 4; k++) {
                float4 a  = shs[cq + 128 * k];
                float4 c2 = shq[cq + 128 * k];
                s.x += a.x; s.y += a.y; s.z += a.z; s.w += a.w;
                q.x += c2.x; q.y += c2.y; q.z += c2.z; q.w += c2.w;
            }
            const int col0 = 4 * cq;
            g_psum[(size_t)(col0 + 0) * GRID + b] = s.x;
            g_psum[(size_t)(col0 + 1) * GRID + b] = s.y;
            g_psum[(size_t)(col0 + 2) * GRID + b] = s.z;
            g_psum[(size_t)(col0 + 3) * GRID + b] = s.w;
            g_psq [(size_t)(col0 + 0) * GRID + b] = q.x;
            g_psq [(size_t)(col0 + 1) * GRID + b] = q.y;
            g_psq [(size_t)(col0 + 2) * GRID + b] = q.z;
            g_psq [(size_t)(col0 + 3) * GRID + b] = q.w;
        }
    }

    // ---------------- Barrier 1: all partials visible ----------------
    grid_barrier(&g_bar0, tid);

    // ---------------- Finalize: block b handles columns b, b+GRID ----------
    {
        __shared__ float ss[16];
        __shared__ float sq[16];
        for (int c = b; c < DCOLS; c += GRID) {
            float s = 0.f, q = 0.f;
            if (tid < GRID) {
                s = g_psum[(size_t)c * GRID + tid];
                q = g_psq [(size_t)c * GRID + tid];
            }
            #pragma unroll
            for (int off = 16; off > 0; off >>= 1) {
                s += __shfl_down_sync(0xFFFFFFFFu, s, off);
                q += __shfl_down_sync(0xFFFFFFFFu, q, off);
            }
            const int warp = tid >> 5;
            const int lane = tid & 31;
            if (lane == 0) { ss[warp] = s; sq[warp] = q; }
            __syncthreads();
            if (tid < 16) {
                s = ss[tid];
                q = sq[tid];
                #pragma unroll
                for (int off = 8; off > 0; off >>= 1) {
                    s += __shfl_down_sync(0x0000FFFFu, s, off);
                    q += __shfl_down_sync(0x0000FFFFu, q, off);
                }
                if (tid == 0) {
                    const float inv_n = 1.0f / (float)NROWS;
                    float mean = s * inv_n;
                    float var  = fmaf(-mean, mean, q * inv_n);
                    float inv  = rsqrtf(var);        // no epsilon (matches reference)
                    float sc   = inv * gamma[c];
                    g_scale[c] = sc;
                    g_shift[c] = fmaf(-mean, sc, beta[c]);
                }
            }
            __syncthreads();
        }
    }

    // ---------------- Barrier 2: scale/shift visible ----------------
    grid_barrier(&g_bar1, tid);

    const float4 sc = reinterpret_cast<const float4*>(g_scale)[cq];
    const float4 sh = reinterpret_cast<const float4*>(g_shift)[cq];

    // ---------------- Phase 2: normalize region BACK-TO-FRONT --------------
    // LIFO order against phase 1 reads -> maximal L2 hit harvest.
    for (int i = nIter - 4; i >= 0; i -= 4) {
        const size_t i0 = base + (size_t)(i + 0) * (4 * DV);
        const size_t i1 = base + (size_t)(i + 1) * (4 * DV);
        const size_t i2 = base + (size_t)(i + 2) * (4 * DV);
        const size_t i3 = base + (size_t)(i + 3) * (4 * DV);
        float4 x0 = Xv[i0];
        float4 x1 = Xv[i1];
        float4 x2 = Xv[i2];
        float4 x3 = Xv[i3];
        float4 y;
        y.x = fmaf(x3.x, sc.x, sh.x); y.y = fmaf(x3.y, sc.y, sh.y);
        y.z = fmaf(x3.z, sc.z, sh.z); y.w = fmaf(x3.w, sc.w, sh.w);
        __stcs(&Yv[i3], y);
        y.x = fmaf(x2.x, sc.x, sh.x); y.y = fmaf(x2.y, sc.y, sh.y);
        y.z = fmaf(x2.z, sc.z, sh.z); y.w = fmaf(x2.w, sc.w, sh.w);
        __stcs(&Yv[i2], y);
        y.x = fmaf(x1.x, sc.x, sh.x); y.y = fmaf(x1.y, sc.y, sh.y);
        y.z = fmaf(x1.z, sc.z, sh.z); y.w = fmaf(x1.w, sc.w, sh.w);
        __stcs(&Yv[i1], y);
        y.x = fmaf(x0.x, sc.x, sh.x); y.y = fmaf(x0.y, sc.y, sh.y);
        y.z = fmaf(x0.z, sc.z, sh.z); y.w = fmaf(x0.w, sc.w, sh.w);
        __stcs(&Yv[i0], y);
    }
}

// ---------------------------------------------------------------------------
extern "C" void kernel_launch(void* const* d_in, const int* in_sizes, int n_in,
                              void* d_out, int out_size) {
    const float* X     = (const float*)d_in[0];
    const float* gamma = (const float*)d_in[1];
    const float* beta  = (const float*)d_in[2];
    float*       Y     = (float*)d_out;

    bn_init_kernel<<<1, 1>>>();
    bn_fused_kernel<<<GRID, NTH>>>((const float4*)X, (float4*)Y, gamma, beta);
}